// round 5
// baseline (speedup 1.0000x reference)
#include <cuda_runtime.h>
#include <cuda_bf16.h>
#include <math.h>

// ---------------- model dims ----------------
#define Bz   2
#define Ss   1024
#define Tt   (Bz*Ss)        // 2048 tokens
#define Dd   1024
#define Hh   16
#define KVh  4
#define HDd  64
#define Ll   4
#define Ee   8
#define Ff   1024
#define Vv   32000

// ---------------- scratch (device globals; no allocation) ----------------
__device__ float g_x[Tt*Dd];
__device__ float g_h[Tt*Dd];
__device__ float g_q[Tt*Hh*HDd];
__device__ float g_k[Tt*KVh*HDd];
__device__ float g_v[Tt*KVh*HDd];
__device__ float g_o[Tt*Hh*HDd];
__device__ float g_scores[(size_t)Bz*Hh*Ss*Ss];   // 134 MB
__device__ float g_gbuf[Tt*Ff];
__device__ float g_ubuf[Tt*Ff];
__device__ int   g_eidx[Ee*Tt];
__device__ float g_egate[Ee*Tt];
__device__ int   g_ecnt[Ee];

// ---------------- helpers ----------------
__device__ __forceinline__ float blockReduceSum256(float v) {
    __shared__ float sh[32];
    int lane = threadIdx.x & 31, wid = threadIdx.x >> 5;
    #pragma unroll
    for (int o = 16; o; o >>= 1) v += __shfl_xor_sync(0xffffffffu, v, o);
    if (lane == 0) sh[wid] = v;
    __syncthreads();
    int nw = (blockDim.x + 31) >> 5;
    float r = (threadIdx.x < nw) ? sh[threadIdx.x] : 0.f;
    if (wid == 0) {
        #pragma unroll
        for (int o = 16; o; o >>= 1) r += __shfl_xor_sync(0xffffffffu, r, o);
        if (lane == 0) sh[0] = r;
    }
    __syncthreads();
    float out = sh[0];
    __syncthreads();
    return out;
}

__device__ __forceinline__ float blockReduceMax256(float v) {
    __shared__ float sh[32];
    int lane = threadIdx.x & 31, wid = threadIdx.x >> 5;
    #pragma unroll
    for (int o = 16; o; o >>= 1) v = fmaxf(v, __shfl_xor_sync(0xffffffffu, v, o));
    if (lane == 0) sh[wid] = v;
    __syncthreads();
    int nw = (blockDim.x + 31) >> 5;
    float r = (threadIdx.x < nw) ? sh[threadIdx.x] : -INFINITY;
    if (wid == 0) {
        #pragma unroll
        for (int o = 16; o; o >>= 1) r = fmaxf(r, __shfl_xor_sync(0xffffffffu, r, o));
        if (lane == 0) sh[0] = r;
    }
    __syncthreads();
    float out = sh[0];
    __syncthreads();
    return out;
}

// ---------------- kernels ----------------
__global__ void embed_k(const int* __restrict__ tok, const float* __restrict__ emb,
                        float* __restrict__ x) {
    int i = blockIdx.x * 256 + threadIdx.x;
    int t = i / Dd, d = i % Dd;
    x[i] = emb[(long)tok[t] * Dd + d];
}

__global__ void rmsnorm_k(const float* __restrict__ x, const float* __restrict__ w,
                          float* __restrict__ out) {
    int row = blockIdx.x;
    const float* xr = x + (long)row * Dd;
    float* orow = out + (long)row * Dd;
    float ss = 0.f;
    #pragma unroll
    for (int i = 0; i < 4; i++) {
        float v = xr[threadIdx.x + i * 256];
        ss += v * v;
    }
    float tot = blockReduceSum256(ss);
    float scale = rsqrtf(tot / (float)Dd + 1e-6f);
    #pragma unroll
    for (int i = 0; i < 4; i++) {
        int d = threadIdx.x + i * 256;
        orow[d] = xr[d] * scale * w[d];
    }
}

// per-head RMSNorm + RoPE, in place. block = 64 threads = one (token, head)
__global__ void qknorm_rope_k(float* __restrict__ qk, const float* __restrict__ nw,
                              const int* __restrict__ pos, int nHeads, int ld) {
    int bid = blockIdx.x;
    int t = bid / nHeads, hh = bid % nHeads;
    float* v = qk + (long)t * ld + hh * HDd;
    int d = threadIdx.x;
    float x = v[d];
    // rms over 64 (2 warps)
    float ss = x * x;
    #pragma unroll
    for (int o = 16; o; o >>= 1) ss += __shfl_xor_sync(0xffffffffu, ss, o);
    __shared__ float s2[2];
    if ((d & 31) == 0) s2[d >> 5] = ss;
    __syncthreads();
    float tot = s2[0] + s2[1];
    float scale = rsqrtf(tot / 64.f + 1e-6f);
    float xn = x * scale * nw[d];
    __shared__ float sh[64];
    sh[d] = xn;
    __syncthreads();
    int p = pos[t];
    int fi = d & 31;
    float inv = powf(1e6f, -(float)fi / 32.f);
    float ang = (float)p * inv;
    float c = cosf(ang), s = sinf(ang);
    float other = (d < 32) ? sh[d + 32] : sh[d - 32];
    float rot = (d < 32) ? -other : other;
    v[d] = xn * c + rot * s;
}

// causal softmax over scores rows; zero-fills j>q
__global__ void softmax_k(float* __restrict__ scores) {
    long row = blockIdx.x;                 // B*H*S rows
    int q = (int)(row % Ss);
    float* p = scores + row * Ss;
    int valid = q + 1;
    float mx = -INFINITY;
    for (int j = threadIdx.x; j < valid; j += 256) mx = fmaxf(mx, p[j]);
    mx = blockReduceMax256(mx);
    float sum = 0.f;
    for (int j = threadIdx.x; j < valid; j += 256) {
        float e = expf(p[j] - mx);
        p[j] = e;
        sum += e;
    }
    sum = blockReduceSum256(sum);
    float inv = 1.f / sum;
    for (int j = threadIdx.x; j < valid; j += 256) p[j] *= inv;
    for (int j = valid + threadIdx.x; j < Ss; j += 256) p[j] = 0.f;
}

__global__ void zero_cnt_k(int* c) { if (threadIdx.x < Ee) c[threadIdx.x] = 0; }

// router: logits = h @ rw [D,E]; top-2; normalize among top-2; fill expert lists
__global__ void router_k(const float* __restrict__ h, const float* __restrict__ rw,
                         int* __restrict__ ecnt, int* __restrict__ eidx,
                         float* __restrict__ egate) {
    int t = blockIdx.x;
    int lane = threadIdx.x & 31, w = threadIdx.x >> 5;   // warp per expert
    const float* hr = h + (long)t * Dd;
    float s = 0.f;
    for (int d = lane; d < Dd; d += 32) s += hr[d] * rw[(long)d * Ee + w];
    #pragma unroll
    for (int o = 16; o; o >>= 1) s += __shfl_xor_sync(0xffffffffu, s, o);
    __shared__ float lg[Ee];
    if (lane == 0) lg[w] = s;
    __syncthreads();
    if (threadIdx.x == 0) {
        int a = 0;
        #pragma unroll
        for (int i = 1; i < Ee; i++) if (lg[i] > lg[a]) a = i;
        int b = (a == 0) ? 1 : 0;
        #pragma unroll
        for (int i = 0; i < Ee; i++) if (i != a && lg[i] > lg[b]) b = i;
        float wa = 1.f / (1.f + expf(lg[b] - lg[a]));
        float wb = 1.f - wa;
        int pa = atomicAdd(&ecnt[a], 1);
        eidx[a * Tt + pa] = t; egate[a * Tt + pa] = wa;
        int pb = atomicAdd(&ecnt[b], 1);
        eidx[b * Tt + pb] = t; egate[b * Tt + pb] = wb;
    }
}

__global__ void silu_mul_k(float* __restrict__ g, const float* __restrict__ u,
                           const int* __restrict__ cnt) {
    long n = (long)(*cnt) * Ff;
    long i = (long)blockIdx.x * 256 + threadIdx.x;
    if (i >= n) return;
    float x = g[i];
    g[i] = (x / (1.f + expf(-x))) * u[i];
}

// ---------------- generic tiled GEMM ----------------
// C[M,N] = alpha * A(MxK) * op(B) (+C if addC); op(B)=B (KxN) or B^T (B is NxK).
// GATHER: A row m -> A[idx[m]]. SCATTER: C[idx[m]] += gate[m]*val (no atomics;
// rows unique within a launch). Batched via blockIdx.z: b=z/nH, h=z%nH.
template<bool TRANSB, bool GATHER, bool SCATTER>
__global__ void __launch_bounds__(256) gemm_k(
    const float* __restrict__ A, const float* __restrict__ B, float* __restrict__ C,
    int M, int N, int K, int lda, int ldb, int ldc,
    float alpha, int addC, int causal,
    const int* __restrict__ idx, const float* __restrict__ gate,
    const int* __restrict__ Mdev,
    long sAb, long sAh, long sBb, long sBh, long sCb, long sCh,
    int nH, int hDiv)
{
    if (Mdev) M = *Mdev;
    int m0 = blockIdx.y * 64, n0 = blockIdx.x * 64;
    if (m0 >= M) return;
    if (causal && n0 >= m0 + 64) return;
    {
        int z = blockIdx.z;
        int b = z / nH, h = z % nH;
        A += (long)b * sAb + (long)h * sAh;
        B += (long)b * sBb + (long)(h / hDiv) * sBh;
        C += (long)b * sCb + (long)h * sCh;
    }
    __shared__ float As[16][65];
    __shared__ float Bs[16][65];
    int tid = threadIdx.x;
    int tx = tid & 15, ty = tid >> 4;
    float acc[4][4];
    #pragma unroll
    for (int i = 0; i < 4; i++)
        #pragma unroll
        for (int j = 0; j < 4; j++) acc[i][j] = 0.f;

    for (int k0 = 0; k0 < K; k0 += 16) {
        #pragma unroll
        for (int i = 0; i < 4; i++) {
            int e = tid + i * 256;
            int m = e >> 4, kk = e & 15;
            float v = 0.f;
            int row = m0 + m;
            if (row < M) {
                int ar = GATHER ? idx[row] : row;
                v = A[(long)ar * lda + k0 + kk];
            }
            As[kk][m] = v;
        }
        if (TRANSB) {
            #pragma unroll
            for (int i = 0; i < 4; i++) {
                int e = tid + i * 256;
                int n = e >> 4, kk = e & 15;
                float v = 0.f;
                if (n0 + n < N) v = B[(long)(n0 + n) * ldb + k0 + kk];
                Bs[kk][n] = v;
            }
        } else {
            #pragma unroll
            for (int i = 0; i < 4; i++) {
                int e = tid + i * 256;
                int kk = e >> 6, n = e & 63;
                float v = 0.f;
                if (n0 + n < N) v = B[(long)(k0 + kk) * ldb + n0 + n];
                Bs[kk][n] = v;
            }
        }
        __syncthreads();
        #pragma unroll
        for (int kk = 0; kk < 16; kk++) {
            float a[4], bb[4];
            #pragma unroll
            for (int i = 0; i < 4; i++) a[i] = As[kk][ty + 16 * i];
            #pragma unroll
            for (int j = 0; j < 4; j++) bb[j] = Bs[kk][tx + 16 * j];
            #pragma unroll
            for (int i = 0; i < 4; i++)
                #pragma unroll
                for (int j = 0; j < 4; j++)
                    acc[i][j] = fmaf(a[i], bb[j], acc[i][j]);
        }
        __syncthreads();
    }

    #pragma unroll
    for (int i = 0; i < 4; i++) {
        int m = m0 + ty + 16 * i;
        if (m >= M) continue;
        #pragma unroll
        for (int j = 0; j < 4; j++) {
            int n = n0 + tx + 16 * j;
            if (n >= N) continue;
            float v = alpha * acc[i][j];
            if (SCATTER) {
                long off = (long)idx[m] * ldc + n;
                C[off] += gate[m] * v;
            } else {
                long off = (long)m * ldc + n;
                if (addC) v += C[off];
                C[off] = v;
            }
        }
    }
}

// ---------------- host-side launcher ----------------
struct GArgs {
    const float *A, *B; float* C;
    int M, N, K, lda, ldb, ldc;
    float alpha; int addC, causal;
    const int* idx; const float* gate; const int* Mdev;
    int Z; long sAb, sAh, sBb, sBh, sCb, sCh; int nH, hDiv;
};

static void run_gemm(int mode /*0=NN,1=NT,2=NN gather,3=NN scatter*/, const GArgs& a) {
    dim3 grid((a.N + 63) / 64, (a.M + 63) / 64, a.Z);
    dim3 blk(256);
    switch (mode) {
    case 0:
        gemm_k<false,false,false><<<grid, blk>>>(a.A, a.B, a.C, a.M, a.N, a.K, a.lda, a.ldb,
            a.ldc, a.alpha, a.addC, a.causal, a.idx, a.gate, a.Mdev,
            a.sAb, a.sAh, a.sBb, a.sBh, a.sCb, a.sCh, a.nH, a.hDiv);
        break;
    case 1:
        gemm_k<true,false,false><<<grid, blk>>>(a.A, a.B, a.C, a.M, a.N, a.K, a.lda, a.ldb,
            a.ldc, a.alpha, a.addC, a.causal, a.idx, a.gate, a.Mdev,
            a.sAb, a.sAh, a.sBb, a.sBh, a.sCb, a.sCh, a.nH, a.hDiv);
        break;
    case 2:
        gemm_k<false,true,false><<<grid, blk>>>(a.A, a.B, a.C, a.M, a.N, a.K, a.lda, a.ldb,
            a.ldc, a.alpha, a.addC, a.causal, a.idx, a.gate, a.Mdev,
            a.sAb, a.sAh, a.sBb, a.sBh, a.sCb, a.sCh, a.nH, a.hDiv);
        break;
    default:
        gemm_k<false,false,true><<<grid, blk>>>(a.A, a.B, a.C, a.M, a.N, a.K, a.lda, a.ldb,
            a.ldc, a.alpha, a.addC, a.causal, a.idx, a.gate, a.Mdev,
            a.sAb, a.sAh, a.sBb, a.sBh, a.sCb, a.sCh, a.nH, a.hDiv);
        break;
    }
}

static GArgs base_args() {
    GArgs a;
    a.A = a.B = nullptr; a.C = nullptr;
    a.M = a.N = a.K = a.lda = a.ldb = a.ldc = 0;
    a.alpha = 1.f; a.addC = 0; a.causal = 0;
    a.idx = nullptr; a.gate = nullptr; a.Mdev = nullptr;
    a.Z = 1; a.sAb = a.sAh = a.sBb = a.sBh = a.sCb = a.sCh = 0;
    a.nH = 1; a.hDiv = 1;
    return a;
}

extern "C" void kernel_launch(void* const* d_in, const int* in_sizes, int n_in,
                              void* d_out, int out_size) {
    const int*   tok    = (const int*)d_in[0];
    const int*   pos    = (const int*)d_in[1];
    const float* emb    = (const float*)d_in[2];
    const float* attnw  = (const float*)d_in[3];
    const float* wq     = (const float*)d_in[4];
    const float* wk     = (const float*)d_in[5];
    const float* wv     = (const float*)d_in[6];
    const float* qnw    = (const float*)d_in[7];
    const float* knw    = (const float*)d_in[8];
    const float* wo     = (const float*)d_in[9];
    const float* ffnw   = (const float*)d_in[10];
    const float* rw     = (const float*)d_in[11];
    const float* gw     = (const float*)d_in[12];
    const float* uw     = (const float*)d_in[13];
    const float* dw     = (const float*)d_in[14];
    const float* fnw    = (const float*)d_in[15];
    float* out = (float*)d_out;

    float *px, *ph, *pq, *pk, *pv, *po, *pscores, *pgbuf, *pubuf, *pegate;
    int *peidx, *pecnt;
    cudaGetSymbolAddress((void**)&px, g_x);
    cudaGetSymbolAddress((void**)&ph, g_h);
    cudaGetSymbolAddress((void**)&pq, g_q);
    cudaGetSymbolAddress((void**)&pk, g_k);
    cudaGetSymbolAddress((void**)&pv, g_v);
    cudaGetSymbolAddress((void**)&po, g_o);
    cudaGetSymbolAddress((void**)&pscores, g_scores);
    cudaGetSymbolAddress((void**)&pgbuf, g_gbuf);
    cudaGetSymbolAddress((void**)&pubuf, g_ubuf);
    cudaGetSymbolAddress((void**)&pegate, g_egate);
    cudaGetSymbolAddress((void**)&peidx, g_eidx);
    cudaGetSymbolAddress((void**)&pecnt, g_ecnt);

    // embed
    embed_k<<<(Tt * Dd) / 256, 256>>>(tok, emb, px);

    for (int l = 0; l < Ll; l++) {
        // ---- attention ----
        rmsnorm_k<<<Tt, 256>>>(px, attnw + (long)l * Dd, ph);

        { GArgs a = base_args(); a.A = ph; a.B = wq + (long)l * Dd * (Hh * HDd); a.C = pq;
          a.M = Tt; a.N = Hh * HDd; a.K = Dd; a.lda = Dd; a.ldb = Hh * HDd; a.ldc = Hh * HDd;
          run_gemm(0, a); }
        { GArgs a = base_args(); a.A = ph; a.B = wk + (long)l * Dd * (KVh * HDd); a.C = pk;
          a.M = Tt; a.N = KVh * HDd; a.K = Dd; a.lda = Dd; a.ldb = KVh * HDd; a.ldc = KVh * HDd;
          run_gemm(0, a); }
        { GArgs a = base_args(); a.A = ph; a.B = wv + (long)l * Dd * (KVh * HDd); a.C = pv;
          a.M = Tt; a.N = KVh * HDd; a.K = Dd; a.lda = Dd; a.ldb = KVh * HDd; a.ldc = KVh * HDd;
          run_gemm(0, a); }

        qknorm_rope_k<<<Tt * Hh, 64>>>(pq, qnw + (long)l * HDd, pos, Hh, Hh * HDd);
        qknorm_rope_k<<<Tt * KVh, 64>>>(pk, knw + (long)l * HDd, pos, KVh, KVh * HDd);

        // scores = Q @ K^T * scale  (batched over B*H, GQA h/4, causal tile skip)
        { GArgs a = base_args(); a.A = pq; a.B = pk; a.C = pscores;
          a.M = Ss; a.N = Ss; a.K = HDd; a.lda = Hh * HDd; a.ldb = KVh * HDd; a.ldc = Ss;
          a.alpha = 0.125f; a.causal = 1;
          a.Z = Bz * Hh; a.nH = Hh; a.hDiv = Hh / KVh;
          a.sAb = (long)Ss * Hh * HDd; a.sAh = HDd;
          a.sBb = (long)Ss * KVh * HDd; a.sBh = HDd;
          a.sCb = (long)Hh * Ss * Ss; a.sCh = (long)Ss * Ss;
          run_gemm(1, a); }

        softmax_k<<<Bz * Hh * Ss, 256>>>(pscores);

        // O = P @ V
        { GArgs a = base_args(); a.A = pscores; a.B = pv; a.C = po;
          a.M = Ss; a.N = HDd; a.K = Ss; a.lda = Ss; a.ldb = KVh * HDd; a.ldc = Hh * HDd;
          a.Z = Bz * Hh; a.nH = Hh; a.hDiv = Hh / KVh;
          a.sAb = (long)Hh * Ss * Ss; a.sAh = (long)Ss * Ss;
          a.sBb = (long)Ss * KVh * HDd; a.sBh = HDd;
          a.sCb = (long)Ss * Hh * HDd; a.sCh = HDd;
          run_gemm(0, a); }

        // x += O @ wo
        { GArgs a = base_args(); a.A = po; a.B = wo + (long)l * (Hh * HDd) * Dd; a.C = px;
          a.M = Tt; a.N = Dd; a.K = Hh * HDd; a.lda = Hh * HDd; a.ldb = Dd; a.ldc = Dd;
          a.addC = 1;
          run_gemm(0, a); }

        // ---- MoE ----
        rmsnorm_k<<<Tt, 256>>>(px, ffnw + (long)l * Dd, ph);
        zero_cnt_k<<<1, 32>>>(pecnt);
        router_k<<<Tt, 256>>>(ph, rw + (long)l * Dd * Ee, pecnt, peidx, pegate);

        for (int e = 0; e < Ee; e++) {
            const int* ecnt_e = pecnt + e;
            const int* idx_e = peidx + e * Tt;
            const float* gate_e = pegate + e * Tt;
            long woff = (long)l * Ee * Dd * Ff + (long)e * Dd * Ff;

            { GArgs a = base_args(); a.A = ph; a.B = gw + woff; a.C = pgbuf;
              a.M = Tt; a.N = Ff; a.K = Dd; a.lda = Dd; a.ldb = Ff; a.ldc = Ff;
              a.idx = idx_e; a.Mdev = ecnt_e;
              run_gemm(2, a); }
            { GArgs a = base_args(); a.A = ph; a.B = uw + woff; a.C = pubuf;
              a.M = Tt; a.N = Ff; a.K = Dd; a.lda = Dd; a.ldb = Ff; a.ldc = Ff;
              a.idx = idx_e; a.Mdev = ecnt_e;
              run_gemm(2, a); }
            silu_mul_k<<<(Tt * Ff) / 256, 256>>>(pgbuf, pubuf, ecnt_e);
            // x[idx] += gate * (act @ down_w)
            { GArgs a = base_args(); a.A = pgbuf; a.B = dw + woff; a.C = px;
              a.M = Tt; a.N = Dd; a.K = Ff; a.lda = Ff; a.ldb = Dd; a.ldc = Dd;
              a.idx = idx_e; a.gate = gate_e; a.Mdev = ecnt_e;
              run_gemm(3, a); }
        }
    }

    // final norm + tied lm_head (NT against tok_emb)
    rmsnorm_k<<<Tt, 256>>>(px, fnw, ph);
    { GArgs a = base_args(); a.A = ph; a.B = emb; a.C = out;
      a.M = Tt; a.N = Vv; a.K = Dd; a.lda = Dd; a.ldb = Dd; a.ldc = Vv;
      run_gemm(1, a); }
}

// round 7
// speedup vs baseline: 1.3737x; 1.3737x over previous
#include <cuda_runtime.h>
#include <cuda_bf16.h>
#include <math.h>
#include <stdint.h>

// ---------------- model dims ----------------
#define Bz   2
#define Ss   1024
#define Tt   (Bz*Ss)        // 2048 tokens
#define Dd   1024
#define Hh   16
#define KVh  4
#define HDd  64
#define Ll   4
#define Ee   8
#define Ff   1024
#define Vv   32000

// ---------------- scratch (device globals; no allocation) ----------------
__device__ float g_x[Tt*Dd];
__device__ float g_h[Tt*Dd];
__device__ float g_q[Tt*Hh*HDd];
__device__ float g_k[Tt*KVh*HDd];
__device__ float g_v[Tt*KVh*HDd];
__device__ float g_o[Tt*Hh*HDd];
__device__ float g_scores[(size_t)Bz*Hh*Ss*Ss];   // 134 MB
__device__ float g_gbuf[Tt*Ff];
__device__ float g_ubuf[Tt*Ff];
__device__ int   g_eidx[Ee*Tt];
__device__ float g_egate[Ee*Tt];
__device__ int   g_ecnt[Ee];

// ---------------- helpers ----------------
__device__ __forceinline__ float tf32r(float x) {
    uint32_t u;
    asm("cvt.rna.tf32.f32 %0, %1;" : "=r"(u) : "f"(x));
    return __uint_as_float(u);
}

__device__ __forceinline__ void mma8(float* c, const uint32_t* a, const uint32_t* b) {
    asm volatile("mma.sync.aligned.m16n8k8.row.col.f32.tf32.tf32.f32 "
                 "{%0,%1,%2,%3}, {%4,%5,%6,%7}, {%8,%9}, {%0,%1,%2,%3};"
                 : "+f"(c[0]), "+f"(c[1]), "+f"(c[2]), "+f"(c[3])
                 : "r"(a[0]), "r"(a[1]), "r"(a[2]), "r"(a[3]),
                   "r"(b[0]), "r"(b[1]));
}

__device__ __forceinline__ float blockReduceSum256(float v) {
    __shared__ float sh[32];
    int lane = threadIdx.x & 31, wid = threadIdx.x >> 5;
    #pragma unroll
    for (int o = 16; o; o >>= 1) v += __shfl_xor_sync(0xffffffffu, v, o);
    if (lane == 0) sh[wid] = v;
    __syncthreads();
    int nw = (blockDim.x + 31) >> 5;
    float r = (threadIdx.x < nw) ? sh[threadIdx.x] : 0.f;
    if (wid == 0) {
        #pragma unroll
        for (int o = 16; o; o >>= 1) r += __shfl_xor_sync(0xffffffffu, r, o);
        if (lane == 0) sh[0] = r;
    }
    __syncthreads();
    float out = sh[0];
    __syncthreads();
    return out;
}

__device__ __forceinline__ float blockReduceMax256(float v) {
    __shared__ float sh[32];
    int lane = threadIdx.x & 31, wid = threadIdx.x >> 5;
    #pragma unroll
    for (int o = 16; o; o >>= 1) v = fmaxf(v, __shfl_xor_sync(0xffffffffu, v, o));
    if (lane == 0) sh[wid] = v;
    __syncthreads();
    int nw = (blockDim.x + 31) >> 5;
    float r = (threadIdx.x < nw) ? sh[threadIdx.x] : -INFINITY;
    if (wid == 0) {
        #pragma unroll
        for (int o = 16; o; o >>= 1) r = fmaxf(r, __shfl_xor_sync(0xffffffffu, r, o));
        if (lane == 0) sh[0] = r;
    }
    __syncthreads();
    float out = sh[0];
    __syncthreads();
    return out;
}

// ---------------- elementwise kernels ----------------
__global__ void embed_k(const int* __restrict__ tok, const float* __restrict__ emb,
                        float* __restrict__ x) {
    int i = blockIdx.x * 256 + threadIdx.x;
    int t = i / Dd, d = i % Dd;
    x[i] = emb[(long)tok[t] * Dd + d];
}

__global__ void rmsnorm_k(const float* __restrict__ x, const float* __restrict__ w,
                          float* __restrict__ out) {
    int row = blockIdx.x;
    const float* xr = x + (long)row * Dd;
    float* orow = out + (long)row * Dd;
    float ss = 0.f;
    #pragma unroll
    for (int i = 0; i < 4; i++) {
        float v = xr[threadIdx.x + i * 256];
        ss += v * v;
    }
    float tot = blockReduceSum256(ss);
    float scale = rsqrtf(tot / (float)Dd + 1e-6f);
    #pragma unroll
    for (int i = 0; i < 4; i++) {
        int d = threadIdx.x + i * 256;
        orow[d] = xr[d] * scale * w[d];
    }
}

// per-head RMSNorm + RoPE, in place. block = 64 threads = one (token, head)
__global__ void qknorm_rope_k(float* __restrict__ qk, const float* __restrict__ nw,
                              const int* __restrict__ pos, int nHeads, int ld) {
    int bid = blockIdx.x;
    int t = bid / nHeads, hh = bid % nHeads;
    float* v = qk + (long)t * ld + hh * HDd;
    int d = threadIdx.x;
    float x = v[d];
    float ss = x * x;
    #pragma unroll
    for (int o = 16; o; o >>= 1) ss += __shfl_xor_sync(0xffffffffu, ss, o);
    __shared__ float s2[2];
    if ((d & 31) == 0) s2[d >> 5] = ss;
    __syncthreads();
    float tot = s2[0] + s2[1];
    float scale = rsqrtf(tot / 64.f + 1e-6f);
    float xn = x * scale * nw[d];
    __shared__ float sh[64];
    sh[d] = xn;
    __syncthreads();
    int p = pos[t];
    int fi = d & 31;
    float inv = powf(1e6f, -(float)fi / 32.f);
    float ang = (float)p * inv;
    float c = cosf(ang), s = sinf(ang);
    float other = (d < 32) ? sh[d + 32] : sh[d - 32];
    float rot = (d < 32) ? -other : other;
    v[d] = xn * c + rot * s;
}

// causal softmax over scores rows; zero-fills j>q
__global__ void softmax_k(float* __restrict__ scores) {
    long row = blockIdx.x;                 // B*H*S rows
    int q = (int)(row % Ss);
    float* p = scores + row * Ss;
    int valid = q + 1;
    float mx = -INFINITY;
    for (int j = threadIdx.x; j < valid; j += 256) mx = fmaxf(mx, p[j]);
    mx = blockReduceMax256(mx);
    float sum = 0.f;
    for (int j = threadIdx.x; j < valid; j += 256) {
        float e = expf(p[j] - mx);
        p[j] = e;
        sum += e;
    }
    sum = blockReduceSum256(sum);
    float inv = 1.f / sum;
    for (int j = threadIdx.x; j < valid; j += 256) p[j] *= inv;
    for (int j = valid + threadIdx.x; j < Ss; j += 256) p[j] = 0.f;
}

__global__ void zero_cnt_k(int* c) { if (threadIdx.x < Ee) c[threadIdx.x] = 0; }

// router: logits = h @ rw [D,E]; top-2; normalize among top-2; fill expert lists
__global__ void router_k(const float* __restrict__ h, const float* __restrict__ rw,
                         int* __restrict__ ecnt, int* __restrict__ eidx,
                         float* __restrict__ egate) {
    int t = blockIdx.x;
    int lane = threadIdx.x & 31, w = threadIdx.x >> 5;   // warp per expert
    const float* hr = h + (long)t * Dd;
    float s = 0.f;
    for (int d = lane; d < Dd; d += 32) s += hr[d] * rw[(long)d * Ee + w];
    #pragma unroll
    for (int o = 16; o; o >>= 1) s += __shfl_xor_sync(0xffffffffu, s, o);
    __shared__ float lg[Ee];
    if (lane == 0) lg[w] = s;
    __syncthreads();
    if (threadIdx.x == 0) {
        int a = 0;
        #pragma unroll
        for (int i = 1; i < Ee; i++) if (lg[i] > lg[a]) a = i;
        int b = (a == 0) ? 1 : 0;
        #pragma unroll
        for (int i = 0; i < Ee; i++) if (i != a && lg[i] > lg[b]) b = i;
        float wa = 1.f / (1.f + expf(lg[b] - lg[a]));
        float wb = 1.f - wa;
        int pa = atomicAdd(&ecnt[a], 1);
        eidx[a * Tt + pa] = t; egate[a * Tt + pa] = wa;
        int pb = atomicAdd(&ecnt[b], 1);
        eidx[b * Tt + pb] = t; egate[b * Tt + pb] = wb;
    }
}

__global__ void silu_mul_k(float* __restrict__ g, const float* __restrict__ u,
                           const int* __restrict__ cnt) {
    long n = (long)(*cnt) * Ff;
    long i = (long)blockIdx.x * 256 + threadIdx.x;
    if (i >= n) return;
    float x = g[i];
    g[i] = (x / (1.f + expf(-x))) * u[i];
}

// ---------------- 3xTF32 tensor-core tiled GEMM ----------------
// C[M,N] = alpha * A(MxK) * op(B) (+C if addC); op(B)=B (KxN) or B^T (B is NxK).
// Tile 64x64x16, 128 threads = 4 warps (2x2), warp tile 32x32 via m16n8k8 tf32.
// 3xTF32 compensation: a = a_hi + a_lo (both tf32); a*b ~= ahi*bhi + ahi*blo +
// alo*bhi accumulated in fp32 (lo*lo term ~2^-22, dropped). Near-fp32 accuracy.
// Assumes N % 64 == 0 and K % 16 == 0 (true for every GEMM in this model).
// GATHER: A row m -> A[idx[m]]. SCATTER: C[idx[m]] += gate[m]*val (rows unique).
template<bool TRANSB, bool GATHER, bool SCATTER>
__global__ void __launch_bounds__(128) gemm_k(
    const float* __restrict__ A, const float* __restrict__ B, float* __restrict__ C,
    int M, int N, int K, int lda, int ldb, int ldc,
    float alpha, int addC, int causal,
    const int* __restrict__ idx, const float* __restrict__ gate,
    const int* __restrict__ Mdev,
    long sAb, long sAh, long sBb, long sBh, long sCb, long sCh,
    int nH, int hDiv)
{
    if (Mdev) M = *Mdev;
    int m0 = blockIdx.y * 64, n0 = blockIdx.x * 64;
    if (m0 >= M) return;
    if (causal && n0 >= m0 + 64) return;
    {
        int z = blockIdx.z;
        int b = z / nH, h = z % nH;
        A += (long)b * sAb + (long)h * sAh;
        B += (long)b * sBb + (long)(h / hDiv) * sBh;
        C += (long)b * sCb + (long)h * sCh;
    }

    // [buf][hi/lo] copies. A: stride 20 conflict-free; B: stride 72 conflict-free.
    __shared__ float As[2][2][64][20];
    __shared__ float Bs[2][2][16][72];

    int tid = threadIdx.x;
    int lane = tid & 31, warp = tid >> 5;
    int wm = (warp >> 1) * 32, wn = (warp & 1) * 32;
    int qrow = lane >> 2, qk = lane & 3;

    // A global-load geometry: 2 rows x float4 per thread
    int ar_r = tid >> 2;               // 0..31
    int ac4 = (tid & 3) * 4;
    int gr0 = m0 + ar_r, gr1 = gr0 + 32;
    bool av0 = gr0 < M, av1 = gr1 < M;
    long arow0 = 0, arow1 = 0;
    if (av0) arow0 = (long)(GATHER ? idx[gr0] : gr0) * lda;
    if (av1) arow1 = (long)(GATHER ? idx[gr1] : gr1) * lda;

    // B global-load geometry
    int bnr, bc4;
    if (TRANSB) { bnr = tid >> 2; bc4 = (tid & 3) * 4; }   // n-row 0..31(+32), k-col
    else        { bnr = tid >> 4; bc4 = (tid & 15) * 4; }  // k-row 0..7(+8), n-col

    float4 pa0, pa1, pb0, pb1;
    const float4 z4 = make_float4(0.f, 0.f, 0.f, 0.f);

    float acc[2][4][4];
    #pragma unroll
    for (int mt = 0; mt < 2; mt++)
        #pragma unroll
        for (int nt = 0; nt < 4; nt++)
            #pragma unroll
            for (int i = 0; i < 4; i++) acc[mt][nt][i] = 0.f;

    auto LDG = [&](int k0) {
        pa0 = av0 ? *(const float4*)(A + arow0 + k0 + ac4) : z4;
        pa1 = av1 ? *(const float4*)(A + arow1 + k0 + ac4) : z4;
        if (TRANSB) {
            pb0 = *(const float4*)(B + (long)(n0 + bnr) * ldb + k0 + bc4);
            pb1 = *(const float4*)(B + (long)(n0 + bnr + 32) * ldb + k0 + bc4);
        } else {
            pb0 = *(const float4*)(B + (long)(k0 + bnr) * ldb + n0 + bc4);
            pb1 = *(const float4*)(B + (long)(k0 + bnr + 8) * ldb + n0 + bc4);
        }
    };

    auto put = [&](float* hi, float* lo, float v) {
        float h = tf32r(v);
        *hi = h;
        *lo = tf32r(v - h);
    };

    auto STS = [&](int buf) {
        put(&As[buf][0][ar_r][ac4 + 0], &As[buf][1][ar_r][ac4 + 0], pa0.x);
        put(&As[buf][0][ar_r][ac4 + 1], &As[buf][1][ar_r][ac4 + 1], pa0.y);
        put(&As[buf][0][ar_r][ac4 + 2], &As[buf][1][ar_r][ac4 + 2], pa0.z);
        put(&As[buf][0][ar_r][ac4 + 3], &As[buf][1][ar_r][ac4 + 3], pa0.w);
        put(&As[buf][0][ar_r + 32][ac4 + 0], &As[buf][1][ar_r + 32][ac4 + 0], pa1.x);
        put(&As[buf][0][ar_r + 32][ac4 + 1], &As[buf][1][ar_r + 32][ac4 + 1], pa1.y);
        put(&As[buf][0][ar_r + 32][ac4 + 2], &As[buf][1][ar_r + 32][ac4 + 2], pa1.z);
        put(&As[buf][0][ar_r + 32][ac4 + 3], &As[buf][1][ar_r + 32][ac4 + 3], pa1.w);
        if (TRANSB) {
            put(&Bs[buf][0][bc4 + 0][bnr], &Bs[buf][1][bc4 + 0][bnr], pb0.x);
            put(&Bs[buf][0][bc4 + 1][bnr], &Bs[buf][1][bc4 + 1][bnr], pb0.y);
            put(&Bs[buf][0][bc4 + 2][bnr], &Bs[buf][1][bc4 + 2][bnr], pb0.z);
            put(&Bs[buf][0][bc4 + 3][bnr], &Bs[buf][1][bc4 + 3][bnr], pb0.w);
            put(&Bs[buf][0][bc4 + 0][bnr + 32], &Bs[buf][1][bc4 + 0][bnr + 32], pb1.x);
            put(&Bs[buf][0][bc4 + 1][bnr + 32], &Bs[buf][1][bc4 + 1][bnr + 32], pb1.y);
            put(&Bs[buf][0][bc4 + 2][bnr + 32], &Bs[buf][1][bc4 + 2][bnr + 32], pb1.z);
            put(&Bs[buf][0][bc4 + 3][bnr + 32], &Bs[buf][1][bc4 + 3][bnr + 32], pb1.w);
        } else {
            put(&Bs[buf][0][bnr][bc4 + 0], &Bs[buf][1][bnr][bc4 + 0], pb0.x);
            put(&Bs[buf][0][bnr][bc4 + 1], &Bs[buf][1][bnr][bc4 + 1], pb0.y);
            put(&Bs[buf][0][bnr][bc4 + 2], &Bs[buf][1][bnr][bc4 + 2], pb0.z);
            put(&Bs[buf][0][bnr][bc4 + 3], &Bs[buf][1][bnr][bc4 + 3], pb0.w);
            put(&Bs[buf][0][bnr + 8][bc4 + 0], &Bs[buf][1][bnr + 8][bc4 + 0], pb1.x);
            put(&Bs[buf][0][bnr + 8][bc4 + 1], &Bs[buf][1][bnr + 8][bc4 + 1], pb1.y);
            put(&Bs[buf][0][bnr + 8][bc4 + 2], &Bs[buf][1][bnr + 8][bc4 + 2], pb1.z);
            put(&Bs[buf][0][bnr + 8][bc4 + 3], &Bs[buf][1][bnr + 8][bc4 + 3], pb1.w);
        }
    };

    auto COMPUTE = [&](int buf) {
        #pragma unroll
        for (int ks = 0; ks < 2; ks++) {
            int kk = ks * 8 + qk;
            uint32_t afh[2][4], afl[2][4];
            #pragma unroll
            for (int mt = 0; mt < 2; mt++) {
                int r = wm + mt * 16 + qrow;
                afh[mt][0] = __float_as_uint(As[buf][0][r][kk]);
                afh[mt][1] = __float_as_uint(As[buf][0][r + 8][kk]);
                afh[mt][2] = __float_as_uint(As[buf][0][r][kk + 4]);
                afh[mt][3] = __float_as_uint(As[buf][0][r + 8][kk + 4]);
                afl[mt][0] = __float_as_uint(As[buf][1][r][kk]);
                afl[mt][1] = __float_as_uint(As[buf][1][r + 8][kk]);
                afl[mt][2] = __float_as_uint(As[buf][1][r][kk + 4]);
                afl[mt][3] = __float_as_uint(As[buf][1][r + 8][kk + 4]);
            }
            uint32_t bfh[4][2], bfl[4][2];
            #pragma unroll
            for (int nt = 0; nt < 4; nt++) {
                int cn = wn + nt * 8 + qrow;
                bfh[nt][0] = __float_as_uint(Bs[buf][0][kk][cn]);
                bfh[nt][1] = __float_as_uint(Bs[buf][0][kk + 4][cn]);
                bfl[nt][0] = __float_as_uint(Bs[buf][1][kk][cn]);
                bfl[nt][1] = __float_as_uint(Bs[buf][1][kk + 4][cn]);
            }
            #pragma unroll
            for (int mt = 0; mt < 2; mt++)
                #pragma unroll
                for (int nt = 0; nt < 4; nt++) {
                    mma8(acc[mt][nt], afh[mt], bfl[nt]);   // hi*lo
                    mma8(acc[mt][nt], afl[mt], bfh[nt]);   // lo*hi
                    mma8(acc[mt][nt], afh[mt], bfh[nt]);   // hi*hi
                }
        }
    };

    int KT = K >> 4;
    LDG(0);
    STS(0);
    __syncthreads();
    for (int kt = 0; kt < KT; kt++) {
        int cur = kt & 1;
        bool more = (kt + 1) < KT;
        if (more) LDG((kt + 1) * 16);
        COMPUTE(cur);
        if (more) {
            __syncthreads();
            STS(cur ^ 1);
            __syncthreads();
        }
    }

    // ---- epilogue ----
    #pragma unroll
    for (int mt = 0; mt < 2; mt++) {
        #pragma unroll
        for (int half = 0; half < 2; half++) {   // c0/c1 vs c2/c3 (row, row+8)
            int m = m0 + wm + mt * 16 + qrow + half * 8;
            if (m >= M) continue;
            float gm = 0.f;
            long crow;
            if (SCATTER) { crow = (long)idx[m] * ldc; gm = gate[m]; }
            else         { crow = (long)m * ldc; }
            #pragma unroll
            for (int nt = 0; nt < 4; nt++) {
                int col = n0 + wn + nt * 8 + 2 * qk;
                float v0 = alpha * acc[mt][nt][half * 2 + 0];
                float v1 = alpha * acc[mt][nt][half * 2 + 1];
                float2* cp = (float2*)(C + crow + col);
                if (SCATTER) {
                    float2 old = *cp;
                    old.x += gm * v0; old.y += gm * v1;
                    *cp = old;
                } else if (addC) {
                    float2 old = *cp;
                    old.x += v0; old.y += v1;
                    *cp = old;
                } else {
                    *cp = make_float2(v0, v1);
                }
            }
        }
    }
}

// ---------------- host-side launcher ----------------
struct GArgs {
    const float *A, *B; float* C;
    int M, N, K, lda, ldb, ldc;
    float alpha; int addC, causal;
    const int* idx; const float* gate; const int* Mdev;
    int Z; long sAb, sAh, sBb, sBh, sCb, sCh; int nH, hDiv;
};

static void run_gemm(int mode /*0=NN,1=NT,2=NN gather,3=NN scatter*/, const GArgs& a) {
    dim3 grid((a.N + 63) / 64, (a.M + 63) / 64, a.Z);
    dim3 blk(128);
    switch (mode) {
    case 0:
        gemm_k<false,false,false><<<grid, blk>>>(a.A, a.B, a.C, a.M, a.N, a.K, a.lda, a.ldb,
            a.ldc, a.alpha, a.addC, a.causal, a.idx, a.gate, a.Mdev,
            a.sAb, a.sAh, a.sBb, a.sBh, a.sCb, a.sCh, a.nH, a.hDiv);
        break;
    case 1:
        gemm_k<true,false,false><<<grid, blk>>>(a.A, a.B, a.C, a.M, a.N, a.K, a.lda, a.ldb,
            a.ldc, a.alpha, a.addC, a.causal, a.idx, a.gate, a.Mdev,
            a.sAb, a.sAh, a.sBb, a.sBh, a.sCb, a.sCh, a.nH, a.hDiv);
        break;
    case 2:
        gemm_k<false,true,false><<<grid, blk>>>(a.A, a.B, a.C, a.M, a.N, a.K, a.lda, a.ldb,
            a.ldc, a.alpha, a.addC, a.causal, a.idx, a.gate, a.Mdev,
            a.sAb, a.sAh, a.sBb, a.sBh, a.sCb, a.sCh, a.nH, a.hDiv);
        break;
    default:
        gemm_k<false,false,true><<<grid, blk>>>(a.A, a.B, a.C, a.M, a.N, a.K, a.lda, a.ldb,
            a.ldc, a.alpha, a.addC, a.causal, a.idx, a.gate, a.Mdev,
            a.sAb, a.sAh, a.sBb, a.sBh, a.sCb, a.sCh, a.nH, a.hDiv);
        break;
    }
}

static GArgs base_args() {
    GArgs a;
    a.A = a.B = nullptr; a.C = nullptr;
    a.M = a.N = a.K = a.lda = a.ldb = a.ldc = 0;
    a.alpha = 1.f; a.addC = 0; a.causal = 0;
    a.idx = nullptr; a.gate = nullptr; a.Mdev = nullptr;
    a.Z = 1; a.sAb = a.sAh = a.sBb = a.sBh = a.sCb = a.sCh = 0;
    a.nH = 1; a.hDiv = 1;
    return a;
}

extern "C" void kernel_launch(void* const* d_in, const int* in_sizes, int n_in,
                              void* d_out, int out_size) {
    const int*   tok    = (const int*)d_in[0];
    const int*   pos    = (const int*)d_in[1];
    const float* emb    = (const float*)d_in[2];
    const float* attnw  = (const float*)d_in[3];
    const float* wq     = (const float*)d_in[4];
    const float* wk     = (const float*)d_in[5];
    const float* wv     = (const float*)d_in[6];
    const float* qnw    = (const float*)d_in[7];
    const float* knw    = (const float*)d_in[8];
    const float* wo     = (const float*)d_in[9];
    const float* ffnw   = (const float*)d_in[10];
    const float* rw     = (const float*)d_in[11];
    const float* gw     = (const float*)d_in[12];
    const float* uw     = (const float*)d_in[13];
    const float* dw     = (const float*)d_in[14];
    const float* fnw    = (const float*)d_in[15];
    float* out = (float*)d_out;

    float *px, *ph, *pq, *pk, *pv, *po, *pscores, *pgbuf, *pubuf, *pegate;
    int *peidx, *pecnt;
    cudaGetSymbolAddress((void**)&px, g_x);
    cudaGetSymbolAddress((void**)&ph, g_h);
    cudaGetSymbolAddress((void**)&pq, g_q);
    cudaGetSymbolAddress((void**)&pk, g_k);
    cudaGetSymbolAddress((void**)&pv, g_v);
    cudaGetSymbolAddress((void**)&po, g_o);
    cudaGetSymbolAddress((void**)&pscores, g_scores);
    cudaGetSymbolAddress((void**)&pgbuf, g_gbuf);
    cudaGetSymbolAddress((void**)&pubuf, g_ubuf);
    cudaGetSymbolAddress((void**)&pegate, g_egate);
    cudaGetSymbolAddress((void**)&peidx, g_eidx);
    cudaGetSymbolAddress((void**)&pecnt, g_ecnt);

    // embed
    embed_k<<<(Tt * Dd) / 256, 256>>>(tok, emb, px);

    for (int l = 0; l < Ll; l++) {
        // ---- attention ----
        rmsnorm_k<<<Tt, 256>>>(px, attnw + (long)l * Dd, ph);

        { GArgs a = base_args(); a.A = ph; a.B = wq + (long)l * Dd * (Hh * HDd); a.C = pq;
          a.M = Tt; a.N = Hh * HDd; a.K = Dd; a.lda = Dd; a.ldb = Hh * HDd; a.ldc = Hh * HDd;
          run_gemm(0, a); }
        { GArgs a = base_args(); a.A = ph; a.B = wk + (long)l * Dd * (KVh * HDd); a.C = pk;
          a.M = Tt; a.N = KVh * HDd; a.K = Dd; a.lda = Dd; a.ldb = KVh * HDd; a.ldc = KVh * HDd;
          run_gemm(0, a); }
        { GArgs a = base_args(); a.A = ph; a.B = wv + (long)l * Dd * (KVh * HDd); a.C = pv;
          a.M = Tt; a.N = KVh * HDd; a.K = Dd; a.lda = Dd; a.ldb = KVh * HDd; a.ldc = KVh * HDd;
          run_gemm(0, a); }

        qknorm_rope_k<<<Tt * Hh, 64>>>(pq, qnw + (long)l * HDd, pos, Hh, Hh * HDd);
        qknorm_rope_k<<<Tt * KVh, 64>>>(pk, knw + (long)l * HDd, pos, KVh, KVh * HDd);

        // scores = Q @ K^T * scale  (batched over B*H, GQA h/4, causal tile skip)
        { GArgs a = base_args(); a.A = pq; a.B = pk; a.C = pscores;
          a.M = Ss; a.N = Ss; a.K = HDd; a.lda = Hh * HDd; a.ldb = KVh * HDd; a.ldc = Ss;
          a.alpha = 0.125f; a.causal = 1;
          a.Z = Bz * Hh; a.nH = Hh; a.hDiv = Hh / KVh;
          a.sAb = (long)Ss * Hh * HDd; a.sAh = HDd;
          a.sBb = (long)Ss * KVh * HDd; a.sBh = HDd;
          a.sCb = (long)Hh * Ss * Ss; a.sCh = (long)Ss * Ss;
          run_gemm(1, a); }

        softmax_k<<<Bz * Hh * Ss, 256>>>(pscores);

        // O = P @ V
        { GArgs a = base_args(); a.A = pscores; a.B = pv; a.C = po;
          a.M = Ss; a.N = HDd; a.K = Ss; a.lda = Ss; a.ldb = KVh * HDd; a.ldc = Hh * HDd;
          a.Z = Bz * Hh; a.nH = Hh; a.hDiv = Hh / KVh;
          a.sAb = (long)Hh * Ss * Ss; a.sAh = (long)Ss * Ss;
          a.sBb = (long)Ss * KVh * HDd; a.sBh = HDd;
          a.sCb = (long)Ss * Hh * HDd; a.sCh = HDd;
          run_gemm(0, a); }

        // x += O @ wo
        { GArgs a = base_args(); a.A = po; a.B = wo + (long)l * (Hh * HDd) * Dd; a.C = px;
          a.M = Tt; a.N = Dd; a.K = Hh * HDd; a.lda = Hh * HDd; a.ldb = Dd; a.ldc = Dd;
          a.addC = 1;
          run_gemm(0, a); }

        // ---- MoE ----
        rmsnorm_k<<<Tt, 256>>>(px, ffnw + (long)l * Dd, ph);
        zero_cnt_k<<<1, 32>>>(pecnt);
        router_k<<<Tt, 256>>>(ph, rw + (long)l * Dd * Ee, pecnt, peidx, pegate);

        for (int e = 0; e < Ee; e++) {
            const int* ecnt_e = pecnt + e;
            const int* idx_e = peidx + e * Tt;
            const float* gate_e = pegate + e * Tt;
            long woff = (long)l * Ee * Dd * Ff + (long)e * Dd * Ff;

            { GArgs a = base_args(); a.A = ph; a.B = gw + woff; a.C = pgbuf;
              a.M = Tt; a.N = Ff; a.K = Dd; a.lda = Dd; a.ldb = Ff; a.ldc = Ff;
              a.idx = idx_e; a.Mdev = ecnt_e;
              run_gemm(2, a); }
            { GArgs a = base_args(); a.A = ph; a.B = uw + woff; a.C = pubuf;
              a.M = Tt; a.N = Ff; a.K = Dd; a.lda = Dd; a.ldb = Ff; a.ldc = Ff;
              a.idx = idx_e; a.Mdev = ecnt_e;
              run_gemm(2, a); }
            silu_mul_k<<<(Tt * Ff) / 256, 256>>>(pgbuf, pubuf, ecnt_e);
            // x[idx] += gate * (act @ down_w)
            { GArgs a = base_args(); a.A = pgbuf; a.B = dw + woff; a.C = px;
              a.M = Tt; a.N = Dd; a.K = Ff; a.lda = Ff; a.ldb = Dd; a.ldc = Dd;
              a.idx = idx_e; a.gate = gate_e; a.Mdev = ecnt_e;
              run_gemm(3, a); }
        }
    }

    // final norm + tied lm_head (NT against tok_emb)
    rmsnorm_k<<<Tt, 256>>>(px, fnw, ph);
    { GArgs a = base_args(); a.A = ph; a.B = emb; a.C = out;
      a.M = Tt; a.N = Vv; a.K = Dd; a.lda = Dd; a.ldb = Dd; a.ldc = Vv;
      run_gemm(1, a); }
}